// round 1
// baseline (speedup 1.0000x reference)
#include <cuda_runtime.h>
#include <cuda_bf16.h>
#include <cstdint>

#define N_NODES 50000
#define N_EDGES 800000
#define CIN 128
#define HID 128
#define COUT 40

// ---------------- device scratch (static, allocation-free) ----------------
__device__ float g_deg[N_NODES];
__device__ float g_dis[N_NODES];
__device__ int   g_rows[N_EDGES];
__device__ int   g_cols[N_EDGES];
__device__ int   g_flag;                 // 1 = edge_index is int64, 0 = int32
__device__ float g_bufA[N_NODES * HID];  // xw scratch
__device__ float g_bufB[N_NODES * HID];  // agg / h scratch
__device__ float g_bufC[N_NODES * HID];  // agg / h scratch

// ---------------- setup kernels ----------------
__global__ void k_init_deg() {
    int i = blockIdx.x * blockDim.x + threadIdx.x;
    if (i < N_NODES) g_deg[i] = 1.0f;   // self loop
}

// Detect edge_index element width. Values are in [0, 50000), so if the data is
// int64 every odd 32-bit word is zero. Probability of a false positive with
// int32 data across 64 sampled odd words is ~0.
__global__ void k_detect(const unsigned* __restrict__ ei) {
    int lane = threadIdx.x;
    unsigned nz = (ei[2 * lane + 1] != 0u) | (ei[2 * (lane + 32) + 1] != 0u);
    unsigned any = __ballot_sync(0xffffffffu, nz);
    if (lane == 0) g_flag = (any == 0u) ? 1 : 0;
}

__global__ void k_convert(const void* __restrict__ ei) {
    int e = blockIdx.x * blockDim.x + threadIdx.x;
    if (e >= N_EDGES) return;
    int r, c;
    if (g_flag) {
        const long long* p = (const long long*)ei;
        r = (int)p[e];
        c = (int)p[N_EDGES + e];
    } else {
        const int* p = (const int*)ei;
        r = p[e];
        c = p[N_EDGES + e];
    }
    g_rows[e] = r;
    g_cols[e] = c;
    atomicAdd(&g_deg[c], 1.0f);
}

__global__ void k_dis() {
    int i = blockIdx.x * blockDim.x + threadIdx.x;
    if (i < N_NODES) g_dis[i] = rsqrtf(g_deg[i]);
}

// ---------------- GEMM: [N,128] @ [128,128] -> xw, agg = xw*dis^2 ----------
// 64-row tile, 256 threads, 8x4 microtile per thread.
__global__ __launch_bounds__(256) void k_gemm128(
    const float* __restrict__ A, const float* __restrict__ W,
    float* __restrict__ xw, float* __restrict__ agg)
{
    __shared__ float sA[64 * 32];
    __shared__ float sW[32 * 128];
    int tid = threadIdx.x;
    int ty = tid >> 5;          // 0..7  (row group)
    int tx = tid & 31;          // 0..31 (col group of 4)
    int rb = blockIdx.x * 64;

    float4 acc[8];
#pragma unroll
    for (int i = 0; i < 8; i++) acc[i] = make_float4(0.f, 0.f, 0.f, 0.f);

    for (int kk = 0; kk < 4; kk++) {
        // W chunk: rows kk*32..kk*32+31, all 128 cols -> contiguous 4096 floats
        const float4* Wg = (const float4*)(W + kk * 32 * 128);
        float4* sW4 = (float4*)sW;
#pragma unroll
        for (int t = 0; t < 4; t++) sW4[tid + t * 256] = Wg[tid + t * 256];
        // A tile: 64 rows x 32 floats
        float4* sA4 = (float4*)sA;
#pragma unroll
        for (int t = 0; t < 2; t++) {
            int idx = tid + t * 256;           // 0..511
            int row = idx >> 3, q = idx & 7;
            int gr = rb + row;
            float4 v = make_float4(0.f, 0.f, 0.f, 0.f);
            if (gr < N_NODES) v = ((const float4*)A)[gr * 32 + kk * 8 + q];
            sA4[row * 8 + q] = v;
        }
        __syncthreads();
#pragma unroll
        for (int k = 0; k < 32; k++) {
            float4 wf = ((const float4*)sW)[k * 32 + tx];
#pragma unroll
            for (int i = 0; i < 8; i++) {
                float a = sA[(ty * 8 + i) * 32 + k];
                acc[i].x += a * wf.x;
                acc[i].y += a * wf.y;
                acc[i].z += a * wf.z;
                acc[i].w += a * wf.w;
            }
        }
        __syncthreads();
    }
#pragma unroll
    for (int i = 0; i < 8; i++) {
        int gr = rb + ty * 8 + i;
        if (gr < N_NODES) {
            float d = g_dis[gr];
            float d2 = d * d;
            ((float4*)xw)[gr * 32 + tx] = acc[i];
            float4 s = make_float4(acc[i].x * d2, acc[i].y * d2,
                                   acc[i].z * d2, acc[i].w * d2);
            ((float4*)agg)[gr * 32 + tx] = s;
        }
    }
}

// ---------------- GEMM: [N,128] @ [128,40] -> xw40, agg40 = xw*dis^2 -------
// 64-row tile, 320 threads (8 row groups x 40 cols), 8 rows per thread.
__global__ __launch_bounds__(320) void k_gemm40(
    const float* __restrict__ A, const float* __restrict__ W,
    float* __restrict__ xw, float* __restrict__ agg)
{
    __shared__ float sA[64 * 64];
    __shared__ float sW[64 * 40];
    int tid = threadIdx.x;
    int tx = tid % 40;
    int ty = tid / 40;          // 0..7
    int rb = blockIdx.x * 64;

    float acc[8];
#pragma unroll
    for (int i = 0; i < 8; i++) acc[i] = 0.f;

    for (int kk = 0; kk < 2; kk++) {
        // W chunk: contiguous 64*40 floats
        for (int idx = tid; idx < 64 * 40; idx += 320)
            sW[idx] = W[kk * 64 * 40 + idx];
        // A tile: 64 rows x 64 floats
        for (int idx = tid; idx < 1024; idx += 320) {
            int row = idx >> 4, q = idx & 15;
            int gr = rb + row;
            float4 v = make_float4(0.f, 0.f, 0.f, 0.f);
            if (gr < N_NODES) v = ((const float4*)A)[gr * 32 + kk * 16 + q];
            ((float4*)sA)[row * 16 + q] = v;
        }
        __syncthreads();
#pragma unroll 8
        for (int k = 0; k < 64; k++) {
            float w = sW[k * 40 + tx];
#pragma unroll
            for (int i = 0; i < 8; i++)
                acc[i] += sA[(ty * 8 + i) * 64 + k] * w;
        }
        __syncthreads();
    }
#pragma unroll
    for (int i = 0; i < 8; i++) {
        int gr = rb + ty * 8 + i;
        if (gr < N_NODES) {
            float d = g_dis[gr];
            float d2 = d * d;
            xw[gr * 40 + tx] = acc[i];
            agg[gr * 40 + tx] = acc[i] * d2;
        }
    }
}

// ---------------- scatter: warp per edge, vector red ----------------------
__device__ __forceinline__ void red_add_v4(float* p, float4 m) {
    asm volatile("red.global.add.v4.f32 [%0], {%1,%2,%3,%4};"
                 :: "l"(p), "f"(m.x), "f"(m.y), "f"(m.z), "f"(m.w)
                 : "memory");
}

__global__ __launch_bounds__(256) void k_scatter128(
    const float* __restrict__ xw, float* __restrict__ agg)
{
    int w = (blockIdx.x * blockDim.x + threadIdx.x) >> 5;
    int lane = threadIdx.x & 31;
    if (w >= N_EDGES) return;
    int r = g_rows[w];
    int c = g_cols[w];
    float nrm = g_dis[r] * g_dis[c];
    float4 v = ((const float4*)xw)[r * 32 + lane];
    float4 m = make_float4(v.x * nrm, v.y * nrm, v.z * nrm, v.w * nrm);
    red_add_v4(agg + c * 128 + lane * 4, m);
}

__global__ __launch_bounds__(256) void k_scatter40(
    const float* __restrict__ xw, float* __restrict__ agg)
{
    int w = (blockIdx.x * blockDim.x + threadIdx.x) >> 5;
    int lane = threadIdx.x & 31;
    if (w >= N_EDGES) return;
    if (lane >= 10) return;
    int r = g_rows[w];
    int c = g_cols[w];
    float nrm = g_dis[r] * g_dis[c];
    float4 v = ((const float4*)xw)[r * 10 + lane];
    float4 m = make_float4(v.x * nrm, v.y * nrm, v.z * nrm, v.w * nrm);
    red_add_v4(agg + c * 40 + lane * 4, m);
}

// ---------------- bias + relu (in place over agg) --------------------------
__global__ __launch_bounds__(256) void k_biasrelu(
    float* __restrict__ agg, const float* __restrict__ b)
{
    int i = blockIdx.x * blockDim.x + threadIdx.x;   // float4 index
    if (i >= N_NODES * 32) return;
    float4 v = ((float4*)agg)[i];
    float4 bb = ((const float4*)b)[i & 31];
    v.x = fmaxf(v.x + bb.x, 0.f);
    v.y = fmaxf(v.y + bb.y, 0.f);
    v.z = fmaxf(v.z + bb.z, 0.f);
    v.w = fmaxf(v.w + bb.w, 0.f);
    ((float4*)agg)[i] = v;
}

// ---------------- final mean pool ------------------------------------------
__global__ void k_zero_out(float* __restrict__ out, const float* __restrict__ b2) {
    int c = threadIdx.x;
    if (c < COUT) out[c] = b2[c];
}

__global__ __launch_bounds__(320) void k_mean(
    const float* __restrict__ z, float* __restrict__ out)
{
    int tid = threadIdx.x;
    int c = tid % 40;
    int r0 = tid / 40;   // 0..7
    float s = 0.f;
    for (int row = blockIdx.x * 8 + r0; row < N_NODES; row += gridDim.x * 8)
        s += z[row * 40 + c];
    __shared__ float sh[320];
    sh[tid] = s;
    __syncthreads();
    if (r0 == 0) {
        float t = 0.f;
#pragma unroll
        for (int i = 0; i < 8; i++) t += sh[i * 40 + c];
        atomicAdd(&out[c], t * (1.0f / (float)N_NODES));
    }
}

// ---------------- launch ----------------------------------------------------
extern "C" void kernel_launch(void* const* d_in, const int* in_sizes, int n_in,
                              void* d_out, int out_size)
{
    const float* x  = (const float*)d_in[0];
    const void*  ei = d_in[1];
    const float* W0 = (const float*)d_in[2];
    const float* b0 = (const float*)d_in[3];
    const float* W1 = (const float*)d_in[4];
    const float* b1 = (const float*)d_in[5];
    const float* W2 = (const float*)d_in[6];
    const float* b2 = (const float*)d_in[7];
    float* out = (float*)d_out;

    float* bufA; cudaGetSymbolAddress((void**)&bufA, g_bufA);
    float* bufB; cudaGetSymbolAddress((void**)&bufB, g_bufB);
    float* bufC; cudaGetSymbolAddress((void**)&bufC, g_bufC);

    const int nodeBlocks = (N_NODES + 255) / 256;
    const int edgeBlocks = (N_EDGES + 255) / 256;
    const int gemmBlocks = (N_NODES + 63) / 64;
    const int scatBlocks = N_EDGES / 8;          // 8 warps per block, warp/edge
    const int reluBlocks = (N_NODES * 32 + 255) / 256;

    // --- normalization setup ---
    k_init_deg<<<nodeBlocks, 256>>>();
    k_detect<<<1, 32>>>((const unsigned*)ei);
    k_convert<<<edgeBlocks, 256>>>(ei);
    k_dis<<<nodeBlocks, 256>>>();

    // --- layer 1: x -> bufB (h1) ---
    k_gemm128<<<gemmBlocks, 256>>>(x, W0, bufA, bufB);
    k_scatter128<<<scatBlocks, 256>>>(bufA, bufB);
    k_biasrelu<<<reluBlocks, 256>>>(bufB, b0);

    // --- layer 2: bufB -> bufC (h2) ---
    k_gemm128<<<gemmBlocks, 256>>>(bufB, W1, bufA, bufC);
    k_scatter128<<<scatBlocks, 256>>>(bufA, bufC);
    k_biasrelu<<<reluBlocks, 256>>>(bufC, b1);

    // --- layer 3: bufC -> bufB (z, 40 ch) ---
    k_gemm40<<<gemmBlocks, 320>>>(bufC, W2, bufA, bufB);
    k_scatter40<<<scatBlocks, 256>>>(bufA, bufB);

    // --- mean pool (+b2) ---
    k_zero_out<<<1, 64>>>(out, b2);
    k_mean<<<256, 320>>>(bufB, out);
}

// round 3
// speedup vs baseline: 1.5714x; 1.5714x over previous
#include <cuda_runtime.h>
#include <cuda_bf16.h>
#include <cstdint>

#define N_NODES 50000
#define N_EDGES 800000
#define HID 128
#define COUT 40
#define NB_SCAN 196   // ceil(50000/256)

typedef unsigned long long ull;

// ---------------- device scratch (static, allocation-free) ----------------
__device__ float g_dis[N_NODES];
__device__ int   g_cnt[N_NODES];
__device__ int   g_off[N_NODES + 1];
__device__ int   g_cur[N_NODES];
__device__ int   g_bsum[NB_SCAN];
__device__ int   g_csrc[N_EDGES];
__device__ float g_cnrm[N_EDGES];
__device__ int   g_flag;                 // 1 = edge_index is int64, 0 = int32
__device__ float g_bufA[N_NODES * HID];  // xw scratch
__device__ float g_bufB[N_NODES * HID];  // h / z scratch

// ---------------- small helpers ----------------
__device__ __forceinline__ ull pack2(float lo, float hi) {
    ull r; asm("mov.b64 %0,{%1,%2};" : "=l"(r) : "f"(lo), "f"(hi)); return r;
}
__device__ __forceinline__ void unpack2(ull v, float& lo, float& hi) {
    asm("mov.b64 {%0,%1},%2;" : "=f"(lo), "=f"(hi) : "l"(v));
}
__device__ __forceinline__ ull fma2(ull a, ull b, ull c) {
    ull d; asm("fma.rn.f32x2 %0,%1,%2,%3;" : "=l"(d) : "l"(a), "l"(b), "l"(c)); return d;
}

__device__ __forceinline__ void decode_edge(const void* ei, int e, int& r, int& c) {
    if (g_flag) {
        const long long* p = (const long long*)ei;
        r = (int)p[e];
        c = (int)p[N_EDGES + e];
    } else {
        const int* p = (const int*)ei;
        r = p[e];
        c = p[N_EDGES + e];
    }
}

// ---------------- setup kernels ----------------
// Detect edge_index element width: for int64 every odd 32-bit word is zero.
__global__ void k_detect(const unsigned* __restrict__ ei) {
    int lane = threadIdx.x;
    unsigned nz = (ei[2 * lane + 1] != 0u) | (ei[2 * (lane + 32) + 1] != 0u);
    unsigned any = __ballot_sync(0xffffffffu, nz);
    if (lane == 0) g_flag = (any == 0u) ? 1 : 0;
}

__global__ void k_zero_cnt() {
    int i = blockIdx.x * blockDim.x + threadIdx.x;
    if (i < N_NODES) g_cnt[i] = 0;
}

__global__ void k_count(const void* __restrict__ ei) {
    int e = blockIdx.x * blockDim.x + threadIdx.x;
    if (e >= N_EDGES) return;
    int r, c;
    decode_edge(ei, e, r, c);
    atomicAdd(&g_cnt[c], 1);
}

__global__ void k_scan_local() {
    __shared__ int s[256];
    int i = blockIdx.x * 256 + threadIdx.x;
    int v = (i < N_NODES) ? g_cnt[i] : 0;
    s[threadIdx.x] = v;
    __syncthreads();
    for (int d = 1; d < 256; d <<= 1) {
        int t = (threadIdx.x >= d) ? s[threadIdx.x - d] : 0;
        __syncthreads();
        s[threadIdx.x] += t;
        __syncthreads();
    }
    if (i < N_NODES) g_off[i] = s[threadIdx.x] - v;  // exclusive within block
    if (threadIdx.x == 255) g_bsum[blockIdx.x] = s[255];
}

__global__ void k_scan_bsum() {
    __shared__ int s[256];
    int tid = threadIdx.x;
    int v = (tid < NB_SCAN) ? g_bsum[tid] : 0;
    s[tid] = v;
    __syncthreads();
    for (int d = 1; d < 256; d <<= 1) {
        int t = (tid >= d) ? s[tid - d] : 0;
        __syncthreads();
        s[tid] += t;
        __syncthreads();
    }
    if (tid < NB_SCAN) g_bsum[tid] = s[tid] - v;  // exclusive
}

__global__ void k_scan_add() {
    int i = blockIdx.x * 256 + threadIdx.x;
    if (i < N_NODES) {
        int o = g_off[i] + g_bsum[blockIdx.x];
        g_off[i] = o;
        g_cur[i] = o;
        g_dis[i] = rsqrtf((float)g_cnt[i] + 1.0f);
    }
    if (i == 0) g_off[N_NODES] = N_EDGES;
}

__global__ void k_fill(const void* __restrict__ ei) {
    int e = blockIdx.x * blockDim.x + threadIdx.x;
    if (e >= N_EDGES) return;
    int r, c;
    decode_edge(ei, e, r, c);
    int pos = atomicAdd(&g_cur[c], 1);
    g_csrc[pos] = r;
    g_cnrm[pos] = g_dis[r] * g_dis[c];
}

// ---------------- GEMM: [N,128] @ [128,128] -> xw -------------------------
// 128-row x 128-col tile, 256 threads, 8x8 microtile, packed f32x2 FMA.
// Static smem only (32KB): W streamed in 32-k chunks alongside A.
__global__ __launch_bounds__(256) void k_gemm128(
    const float* __restrict__ A, const float* __restrict__ W,
    float* __restrict__ xw)
{
    __shared__ float sW[32 * 128];
    __shared__ float sA[32 * 128];   // k-major, row XOR-swizzled

    int tid = threadIdx.x;
    int ty = tid >> 4;           // 0..15 row group
    int tx = tid & 15;           // 0..15 col group
    int rb = blockIdx.x * 128;

    ull acc[8][4];
#pragma unroll
    for (int i = 0; i < 8; i++)
#pragma unroll
        for (int j = 0; j < 4; j++) acc[i][j] = 0ull;

    const float4* A4 = (const float4*)A;

    for (int kk = 0; kk < 4; kk++) {
        __syncthreads();
        // W chunk: rows kk*32..+31, all 128 cols (4096 floats, contiguous)
        {
            const float4* Wg = (const float4*)(W + kk * 32 * 128);
            float4* sW4 = (float4*)sW;
#pragma unroll
            for (int t = 0; t < 4; t++) sW4[tid + t * 256] = Wg[tid + t * 256];
        }
        // A tile: 128 rows x 32 k, transposed into sA[k][row^] with XOR swizzle
#pragma unroll
        for (int t = 0; t < 4; t++) {
            int idx = tid + t * 256;         // 0..1023
            int row = idx >> 3, q = idx & 7; // q = float4 index within 32 k
            int gr = rb + row;
            float4 v = make_float4(0.f, 0.f, 0.f, 0.f);
            if (gr < N_NODES) v = A4[gr * 32 + kk * 8 + q];
            int xr = row ^ (q << 2);
            sA[(q * 4 + 0) * 128 + xr] = v.x;
            sA[(q * 4 + 1) * 128 + xr] = v.y;
            sA[(q * 4 + 2) * 128 + xr] = v.z;
            sA[(q * 4 + 3) * 128 + xr] = v.w;
        }
        __syncthreads();
#pragma unroll 4
        for (int kl = 0; kl < 32; kl++) {
            int q = kl >> 2;
            float4 a0 = *(const float4*)&sA[kl * 128 + ((ty * 8) ^ (q << 2))];
            float4 a1 = *(const float4*)&sA[kl * 128 + ((ty * 8 + 4) ^ (q << 2))];
            ulonglong2 w01 = *(const ulonglong2*)&sW[kl * 128 + tx * 8];
            ulonglong2 w23 = *(const ulonglong2*)&sW[kl * 128 + tx * 8 + 4];
            ull wp0 = w01.x, wp1 = w01.y, wp2 = w23.x, wp3 = w23.y;
            float ar[8] = {a0.x, a0.y, a0.z, a0.w, a1.x, a1.y, a1.z, a1.w};
#pragma unroll
            for (int i = 0; i < 8; i++) {
                ull ap = pack2(ar[i], ar[i]);
                acc[i][0] = fma2(ap, wp0, acc[i][0]);
                acc[i][1] = fma2(ap, wp1, acc[i][1]);
                acc[i][2] = fma2(ap, wp2, acc[i][2]);
                acc[i][3] = fma2(ap, wp3, acc[i][3]);
            }
        }
    }

    float4* xw4 = (float4*)xw;
#pragma unroll
    for (int i = 0; i < 8; i++) {
        int gr = rb + ty * 8 + i;
        if (gr >= N_NODES) continue;
        float4 o0, o1;
        unpack2(acc[i][0], o0.x, o0.y);
        unpack2(acc[i][1], o0.z, o0.w);
        unpack2(acc[i][2], o1.x, o1.y);
        unpack2(acc[i][3], o1.z, o1.w);
        xw4[gr * 32 + tx * 2] = o0;
        xw4[gr * 32 + tx * 2 + 1] = o1;
    }
}

// ---------------- GEMM: [N,128] @ [128,40] -> xw40 ------------------------
__global__ __launch_bounds__(320) void k_gemm40(
    const float* __restrict__ A, const float* __restrict__ W,
    float* __restrict__ xw)
{
    __shared__ float sA[64 * 64];
    __shared__ float sW[64 * 40];
    int tid = threadIdx.x;
    int tx = tid % 40;
    int ty = tid / 40;          // 0..7
    int rb = blockIdx.x * 64;

    float acc[8];
#pragma unroll
    for (int i = 0; i < 8; i++) acc[i] = 0.f;

    for (int kk = 0; kk < 2; kk++) {
        __syncthreads();
        for (int idx = tid; idx < 64 * 40; idx += 320)
            sW[idx] = W[kk * 64 * 40 + idx];
        for (int idx = tid; idx < 1024; idx += 320) {
            int row = idx >> 4, q = idx & 15;
            int gr = rb + row;
            float4 v = make_float4(0.f, 0.f, 0.f, 0.f);
            if (gr < N_NODES) v = ((const float4*)A)[gr * 32 + kk * 16 + q];
            ((float4*)sA)[row * 16 + q] = v;
        }
        __syncthreads();
#pragma unroll 8
        for (int k = 0; k < 64; k++) {
            float w = sW[k * 40 + tx];
#pragma unroll
            for (int i = 0; i < 8; i++)
                acc[i] += sA[(ty * 8 + i) * 64 + k] * w;
        }
    }
#pragma unroll
    for (int i = 0; i < 8; i++) {
        int gr = rb + ty * 8 + i;
        if (gr < N_NODES) xw[gr * 40 + tx] = acc[i];
    }
}

// ---------------- CSR aggregate (warp per destination node) ---------------
__global__ __launch_bounds__(256) void k_agg128(
    const float* __restrict__ xw, const float* __restrict__ bias,
    float* __restrict__ h, int relu)
{
    int w = blockIdx.x * 8 + (threadIdx.x >> 5);
    int lane = threadIdx.x & 31;
    if (w >= N_NODES) return;
    const float4* xw4 = (const float4*)xw;
    float d = g_dis[w];
    float d2 = d * d;
    float4 self = xw4[w * 32 + lane];
    float4 acc = make_float4(self.x * d2, self.y * d2, self.z * d2, self.w * d2);
    int beg = g_off[w], end = g_off[w + 1];
    for (int e0 = beg; e0 < end; e0 += 32) {
        int idx = e0 + lane;
        int s = 0; float nv = 0.f;
        if (idx < end) { s = g_csrc[idx]; nv = g_cnrm[idx]; }
        int n = min(32, end - e0);
#pragma unroll 4
        for (int j = 0; j < n; j++) {
            int r = __shfl_sync(0xffffffffu, s, j);
            float nw = __shfl_sync(0xffffffffu, nv, j);
            float4 v = xw4[r * 32 + lane];
            acc.x += v.x * nw;
            acc.y += v.y * nw;
            acc.z += v.z * nw;
            acc.w += v.w * nw;
        }
    }
    float4 bb = ((const float4*)bias)[lane];
    acc.x += bb.x; acc.y += bb.y; acc.z += bb.z; acc.w += bb.w;
    if (relu) {
        acc.x = fmaxf(acc.x, 0.f);
        acc.y = fmaxf(acc.y, 0.f);
        acc.z = fmaxf(acc.z, 0.f);
        acc.w = fmaxf(acc.w, 0.f);
    }
    ((float4*)h)[w * 32 + lane] = acc;
}

__global__ __launch_bounds__(256) void k_agg40(
    const float* __restrict__ xw, float* __restrict__ z)
{
    int w = blockIdx.x * 8 + (threadIdx.x >> 5);
    int lane = threadIdx.x & 31;
    if (w >= N_NODES) return;
    const float4* xw4 = (const float4*)xw;
    float d = g_dis[w];
    float d2 = d * d;
    float4 acc = make_float4(0.f, 0.f, 0.f, 0.f);
    if (lane < 10) {
        float4 s = xw4[w * 10 + lane];
        acc = make_float4(s.x * d2, s.y * d2, s.z * d2, s.w * d2);
    }
    int beg = g_off[w], end = g_off[w + 1];
    for (int e0 = beg; e0 < end; e0 += 32) {
        int idx = e0 + lane;
        int s = 0; float nv = 0.f;
        if (idx < end) { s = g_csrc[idx]; nv = g_cnrm[idx]; }
        int n = min(32, end - e0);
#pragma unroll 4
        for (int j = 0; j < n; j++) {
            int r = __shfl_sync(0xffffffffu, s, j);
            float nw = __shfl_sync(0xffffffffu, nv, j);
            if (lane < 10) {
                float4 v = xw4[r * 10 + lane];
                acc.x += v.x * nw;
                acc.y += v.y * nw;
                acc.z += v.z * nw;
                acc.w += v.w * nw;
            }
        }
    }
    if (lane < 10) ((float4*)z)[w * 10 + lane] = acc;
}

// ---------------- final mean pool ------------------------------------------
__global__ void k_zero_out(float* __restrict__ out, const float* __restrict__ b2) {
    int c = threadIdx.x;
    if (c < COUT) out[c] = b2[c];
}

__global__ __launch_bounds__(320) void k_mean(
    const float* __restrict__ z, float* __restrict__ out)
{
    int tid = threadIdx.x;
    int c = tid % 40;
    int r0 = tid / 40;   // 0..7
    float s = 0.f;
    for (int row = blockIdx.x * 8 + r0; row < N_NODES; row += gridDim.x * 8)
        s += z[row * 40 + c];
    __shared__ float sh[320];
    sh[tid] = s;
    __syncthreads();
    if (r0 == 0) {
        float t = 0.f;
#pragma unroll
        for (int i = 0; i < 8; i++) t += sh[i * 40 + c];
        atomicAdd(&out[c], t * (1.0f / (float)N_NODES));
    }
}

// ---------------- launch ----------------------------------------------------
extern "C" void kernel_launch(void* const* d_in, const int* in_sizes, int n_in,
                              void* d_out, int out_size)
{
    const float* x  = (const float*)d_in[0];
    const void*  ei = d_in[1];
    const float* W0 = (const float*)d_in[2];
    const float* b0 = (const float*)d_in[3];
    const float* W1 = (const float*)d_in[4];
    const float* b1 = (const float*)d_in[5];
    const float* W2 = (const float*)d_in[6];
    const float* b2 = (const float*)d_in[7];
    float* out = (float*)d_out;

    float* bufA; cudaGetSymbolAddress((void**)&bufA, g_bufA);
    float* bufB; cudaGetSymbolAddress((void**)&bufB, g_bufB);

    const int edgeBlocks  = (N_EDGES + 255) / 256;   // 3125
    const int gemmBlocks  = (N_NODES + 127) / 128;   // 391
    const int gemm40Blk   = (N_NODES + 63) / 64;     // 782
    const int aggBlocks   = (N_NODES + 7) / 8;       // 6250

    // --- CSR build + normalization ---
    k_detect<<<1, 32>>>((const unsigned*)ei);
    k_zero_cnt<<<NB_SCAN, 256>>>();
    k_count<<<edgeBlocks, 256>>>(ei);
    k_scan_local<<<NB_SCAN, 256>>>();
    k_scan_bsum<<<1, 256>>>();
    k_scan_add<<<NB_SCAN, 256>>>();
    k_fill<<<edgeBlocks, 256>>>(ei);

    // --- layer 1: x -> bufB (h1) ---
    k_gemm128<<<gemmBlocks, 256>>>(x, W0, bufA);
    k_agg128<<<aggBlocks, 256>>>(bufA, b0, bufB, 1);

    // --- layer 2: bufB -> bufB (h2) ---
    k_gemm128<<<gemmBlocks, 256>>>(bufB, W1, bufA);
    k_agg128<<<aggBlocks, 256>>>(bufA, b1, bufB, 1);

    // --- layer 3: bufB -> bufB (z, 40 ch) ---
    k_gemm40<<<gemm40Blk, 320>>>(bufB, W2, bufA);
    k_agg40<<<aggBlocks, 256>>>(bufA, bufB);

    // --- mean pool (+b2) ---
    k_zero_out<<<1, 64>>>(out, b2);
    k_mean<<<256, 320>>>(bufB, out);
}

// round 4
// speedup vs baseline: 1.6245x; 1.0338x over previous
#include <cuda_runtime.h>
#include <cuda_bf16.h>
#include <cstdint>

#define N_NODES 50000
#define N_EDGES 800000
#define HID 128
#define COUT 40
#define NB_SCAN 196   // ceil(50000/256)

typedef unsigned long long ull;

// ---------------- device scratch (static, allocation-free) ----------------
__device__ float g_dis[N_NODES];
__device__ int   g_cnt[N_NODES];
__device__ int   g_off[N_NODES + 1];
__device__ int   g_cur[N_NODES];
__device__ int   g_bsum[NB_SCAN];
__device__ int2  g_epair[N_EDGES];       // {src, __float_as_int(norm)} CSR-ordered
__device__ int   g_flag;                 // 1 = edge_index is int64, 0 = int32
__device__ float g_bufA[N_NODES * HID];  // xw scratch (also int2 staging in setup)
__device__ float g_bufB[N_NODES * HID];  // h / z scratch

// ---------------- small helpers ----------------
__device__ __forceinline__ ull pack2(float lo, float hi) {
    ull r; asm("mov.b64 %0,{%1,%2};" : "=l"(r) : "f"(lo), "f"(hi)); return r;
}
__device__ __forceinline__ void unpack2(ull v, float& lo, float& hi) {
    asm("mov.b64 {%0,%1},%2;" : "=f"(lo), "=f"(hi) : "l"(v));
}
__device__ __forceinline__ ull fma2(ull a, ull b, ull c) {
    ull d; asm("fma.rn.f32x2 %0,%1,%2,%3;" : "=l"(d) : "l"(a), "l"(b), "l"(c)); return d;
}

__device__ __forceinline__ void decode_edge(const void* ei, int e, int& r, int& c) {
    if (g_flag) {
        const long long* p = (const long long*)ei;
        r = (int)p[e];
        c = (int)p[N_EDGES + e];
    } else {
        const int* p = (const int*)ei;
        r = p[e];
        c = p[N_EDGES + e];
    }
}

// ---------------- setup kernels ----------------
// Zero counters; block 0 also detects edge_index element width
// (int64 => every odd 32-bit word is zero, values < 50000).
__global__ void k_zero_detect(const unsigned* __restrict__ ei) {
    int i = blockIdx.x * 256 + threadIdx.x;
    if (i < N_NODES) g_cnt[i] = 0;
    if (blockIdx.x == 0 && threadIdx.x < 32) {
        int lane = threadIdx.x;
        unsigned nz = (ei[2 * lane + 1] != 0u) | (ei[2 * (lane + 32) + 1] != 0u);
        unsigned any = __ballot_sync(0xffffffffu, nz);
        if (lane == 0) g_flag = (any == 0u) ? 1 : 0;
    }
}

// Decode once into staging (int2 per edge) + histogram destinations.
__global__ void k_decode_count(const void* __restrict__ ei, int2* __restrict__ stage) {
    int e = blockIdx.x * blockDim.x + threadIdx.x;
    if (e >= N_EDGES) return;
    int r, c;
    decode_edge(ei, e, r, c);
    stage[e] = make_int2(r, c);
    atomicAdd(&g_cnt[c], 1);
}

__global__ void k_scan_local() {
    __shared__ int s[256];
    int i = blockIdx.x * 256 + threadIdx.x;
    int v = (i < N_NODES) ? g_cnt[i] : 0;
    s[threadIdx.x] = v;
    __syncthreads();
    for (int d = 1; d < 256; d <<= 1) {
        int t = (threadIdx.x >= d) ? s[threadIdx.x - d] : 0;
        __syncthreads();
        s[threadIdx.x] += t;
        __syncthreads();
    }
    if (i < N_NODES) g_off[i] = s[threadIdx.x] - v;  // exclusive within block
    if (threadIdx.x == 255) g_bsum[blockIdx.x] = s[255];
}

__global__ void k_scan_bsum() {
    __shared__ int s[256];
    int tid = threadIdx.x;
    int v = (tid < NB_SCAN) ? g_bsum[tid] : 0;
    s[tid] = v;
    __syncthreads();
    for (int d = 1; d < 256; d <<= 1) {
        int t = (tid >= d) ? s[tid - d] : 0;
        __syncthreads();
        s[tid] += t;
        __syncthreads();
    }
    if (tid < NB_SCAN) g_bsum[tid] = s[tid] - v;  // exclusive
}

__global__ void k_scan_add() {
    int i = blockIdx.x * 256 + threadIdx.x;
    if (i < N_NODES) {
        int o = g_off[i] + g_bsum[blockIdx.x];
        g_off[i] = o;
        g_cur[i] = o;
        g_dis[i] = rsqrtf((float)g_cnt[i] + 1.0f);
    }
    if (i == 0) g_off[N_NODES] = N_EDGES;
}

__global__ void k_fill(const int2* __restrict__ stage) {
    int e = blockIdx.x * blockDim.x + threadIdx.x;
    if (e >= N_EDGES) return;
    int2 rc = stage[e];
    int pos = atomicAdd(&g_cur[rc.y], 1);
    float nrm = g_dis[rc.x] * g_dis[rc.y];
    g_epair[pos] = make_int2(rc.x, __float_as_int(nrm));
}

// ---------------- GEMM: [N,128] @ [128,128] -> xw -------------------------
// 128x128 tile, 256 threads, 8x8 microtile, packed f32x2 FMA, 2 blocks/SM.
__global__ __launch_bounds__(256, 2) void k_gemm128(
    const float* __restrict__ A, const float* __restrict__ W,
    float* __restrict__ xw)
{
    __shared__ float sW[32 * 128];
    __shared__ float sA[32 * 128];   // k-major, row XOR-swizzled

    int tid = threadIdx.x;
    int ty = tid >> 4;           // 0..15 row group
    int tx = tid & 15;           // 0..15 col group
    int rb = blockIdx.x * 128;

    ull acc[8][4];
#pragma unroll
    for (int i = 0; i < 8; i++)
#pragma unroll
        for (int j = 0; j < 4; j++) acc[i][j] = 0ull;

    const float4* A4 = (const float4*)A;

    for (int kk = 0; kk < 4; kk++) {
        __syncthreads();
        // W chunk: rows kk*32..+31, all 128 cols (4096 floats, contiguous)
        {
            const float4* Wg = (const float4*)(W + kk * 32 * 128);
            float4* sW4 = (float4*)sW;
#pragma unroll
            for (int t = 0; t < 4; t++) sW4[tid + t * 256] = Wg[tid + t * 256];
        }
        // A tile: 128 rows x 32 k, transposed into sA[k][row^] with XOR swizzle
#pragma unroll
        for (int t = 0; t < 4; t++) {
            int idx = tid + t * 256;         // 0..1023
            int row = idx >> 3, q = idx & 7; // q = float4 index within 32 k
            int gr = rb + row;
            float4 v = make_float4(0.f, 0.f, 0.f, 0.f);
            if (gr < N_NODES) v = A4[gr * 32 + kk * 8 + q];
            int xr = row ^ (q << 2);
            sA[(q * 4 + 0) * 128 + xr] = v.x;
            sA[(q * 4 + 1) * 128 + xr] = v.y;
            sA[(q * 4 + 2) * 128 + xr] = v.z;
            sA[(q * 4 + 3) * 128 + xr] = v.w;
        }
        __syncthreads();
#pragma unroll 4
        for (int kl = 0; kl < 32; kl++) {
            int q = kl >> 2;
            float4 a0 = *(const float4*)&sA[kl * 128 + ((ty * 8) ^ (q << 2))];
            float4 a1 = *(const float4*)&sA[kl * 128 + ((ty * 8 + 4) ^ (q << 2))];
            ulonglong2 w01 = *(const ulonglong2*)&sW[kl * 128 + tx * 8];
            ulonglong2 w23 = *(const ulonglong2*)&sW[kl * 128 + tx * 8 + 4];
            ull wp0 = w01.x, wp1 = w01.y, wp2 = w23.x, wp3 = w23.y;
            float ar[8] = {a0.x, a0.y, a0.z, a0.w, a1.x, a1.y, a1.z, a1.w};
#pragma unroll
            for (int i = 0; i < 8; i++) {
                ull ap = pack2(ar[i], ar[i]);
                acc[i][0] = fma2(ap, wp0, acc[i][0]);
                acc[i][1] = fma2(ap, wp1, acc[i][1]);
                acc[i][2] = fma2(ap, wp2, acc[i][2]);
                acc[i][3] = fma2(ap, wp3, acc[i][3]);
            }
        }
    }

    float4* xw4 = (float4*)xw;
#pragma unroll
    for (int i = 0; i < 8; i++) {
        int gr = rb + ty * 8 + i;
        if (gr >= N_NODES) continue;
        float4 o0, o1;
        unpack2(acc[i][0], o0.x, o0.y);
        unpack2(acc[i][1], o0.z, o0.w);
        unpack2(acc[i][2], o1.x, o1.y);
        unpack2(acc[i][3], o1.z, o1.w);
        xw4[gr * 32 + tx * 2] = o0;
        xw4[gr * 32 + tx * 2 + 1] = o1;
    }
}

// ---------------- GEMM: [N,128] @ [128,40] -> xw40 ------------------------
__global__ __launch_bounds__(320) void k_gemm40(
    const float* __restrict__ A, const float* __restrict__ W,
    float* __restrict__ xw)
{
    __shared__ float sA[64 * 64];
    __shared__ float sW[64 * 40];
    int tid = threadIdx.x;
    int tx = tid % 40;
    int ty = tid / 40;          // 0..7
    int rb = blockIdx.x * 64;

    float acc[8];
#pragma unroll
    for (int i = 0; i < 8; i++) acc[i] = 0.f;

    for (int kk = 0; kk < 2; kk++) {
        __syncthreads();
        for (int idx = tid; idx < 64 * 40; idx += 320)
            sW[idx] = W[kk * 64 * 40 + idx];
        for (int idx = tid; idx < 1024; idx += 320) {
            int row = idx >> 4, q = idx & 15;
            int gr = rb + row;
            float4 v = make_float4(0.f, 0.f, 0.f, 0.f);
            if (gr < N_NODES) v = ((const float4*)A)[gr * 32 + kk * 16 + q];
            ((float4*)sA)[row * 16 + q] = v;
        }
        __syncthreads();
#pragma unroll 8
        for (int k = 0; k < 64; k++) {
            float w = sW[k * 40 + tx];
#pragma unroll
            for (int i = 0; i < 8; i++)
                acc[i] += sA[(ty * 8 + i) * 64 + k] * w;
        }
    }
#pragma unroll
    for (int i = 0; i < 8; i++) {
        int gr = rb + ty * 8 + i;
        if (gr < N_NODES) xw[gr * 40 + tx] = acc[i];
    }
}

// ---------------- CSR aggregate (warp per destination node) ---------------
// Edge metadata via uniform-address loads (HW broadcast), no shuffles.
__global__ __launch_bounds__(256) void k_agg128(
    const float* __restrict__ xw, const float* __restrict__ bias,
    float* __restrict__ h, int relu)
{
    int w = blockIdx.x * 8 + (threadIdx.x >> 5);
    int lane = threadIdx.x & 31;
    if (w >= N_NODES) return;
    const float4* xw4 = (const float4*)xw;
    float d = g_dis[w];
    float d2 = d * d;
    float4 self = xw4[w * 32 + lane];
    float4 acc = make_float4(self.x * d2, self.y * d2, self.z * d2, self.w * d2);
    int beg = g_off[w], end = g_off[w + 1];
    int e = beg;
    for (; e + 4 <= end; e += 4) {
        int2 p0 = g_epair[e];
        int2 p1 = g_epair[e + 1];
        int2 p2 = g_epair[e + 2];
        int2 p3 = g_epair[e + 3];
        float4 v0 = xw4[p0.x * 32 + lane];
        float4 v1 = xw4[p1.x * 32 + lane];
        float4 v2 = xw4[p2.x * 32 + lane];
        float4 v3 = xw4[p3.x * 32 + lane];
        float n0 = __int_as_float(p0.y), n1 = __int_as_float(p1.y);
        float n2 = __int_as_float(p2.y), n3 = __int_as_float(p3.y);
        acc.x += v0.x * n0; acc.y += v0.y * n0; acc.z += v0.z * n0; acc.w += v0.w * n0;
        acc.x += v1.x * n1; acc.y += v1.y * n1; acc.z += v1.z * n1; acc.w += v1.w * n1;
        acc.x += v2.x * n2; acc.y += v2.y * n2; acc.z += v2.z * n2; acc.w += v2.w * n2;
        acc.x += v3.x * n3; acc.y += v3.y * n3; acc.z += v3.z * n3; acc.w += v3.w * n3;
    }
    for (; e < end; e++) {
        int2 p = g_epair[e];
        float nw = __int_as_float(p.y);
        float4 v = xw4[p.x * 32 + lane];
        acc.x += v.x * nw; acc.y += v.y * nw; acc.z += v.z * nw; acc.w += v.w * nw;
    }
    float4 bb = ((const float4*)bias)[lane];
    acc.x += bb.x; acc.y += bb.y; acc.z += bb.z; acc.w += bb.w;
    if (relu) {
        acc.x = fmaxf(acc.x, 0.f);
        acc.y = fmaxf(acc.y, 0.f);
        acc.z = fmaxf(acc.z, 0.f);
        acc.w = fmaxf(acc.w, 0.f);
    }
    ((float4*)h)[w * 32 + lane] = acc;
}

__global__ __launch_bounds__(256) void k_agg40(
    const float* __restrict__ xw, float* __restrict__ z)
{
    int w = blockIdx.x * 8 + (threadIdx.x >> 5);
    int lane = threadIdx.x & 31;
    if (w >= N_NODES) return;
    const float4* xw4 = (const float4*)xw;
    float d = g_dis[w];
    float d2 = d * d;
    bool act = lane < 10;
    float4 acc = make_float4(0.f, 0.f, 0.f, 0.f);
    if (act) {
        float4 s = xw4[w * 10 + lane];
        acc = make_float4(s.x * d2, s.y * d2, s.z * d2, s.w * d2);
    }
    int beg = g_off[w], end = g_off[w + 1];
    int e = beg;
    for (; e + 2 <= end; e += 2) {
        int2 p0 = g_epair[e];
        int2 p1 = g_epair[e + 1];
        if (act) {
            float n0 = __int_as_float(p0.y), n1 = __int_as_float(p1.y);
            float4 v0 = xw4[p0.x * 10 + lane];
            float4 v1 = xw4[p1.x * 10 + lane];
            acc.x += v0.x * n0; acc.y += v0.y * n0; acc.z += v0.z * n0; acc.w += v0.w * n0;
            acc.x += v1.x * n1; acc.y += v1.y * n1; acc.z += v1.z * n1; acc.w += v1.w * n1;
        }
    }
    for (; e < end; e++) {
        int2 p = g_epair[e];
        if (act) {
            float nw = __int_as_float(p.y);
            float4 v = xw4[p.x * 10 + lane];
            acc.x += v.x * nw; acc.y += v.y * nw; acc.z += v.z * nw; acc.w += v.w * nw;
        }
    }
    if (act) ((float4*)z)[w * 10 + lane] = acc;
}

// ---------------- final mean pool ------------------------------------------
__global__ void k_zero_out(float* __restrict__ out, const float* __restrict__ b2) {
    int c = threadIdx.x;
    if (c < COUT) out[c] = b2[c];
}

__global__ __launch_bounds__(320) void k_mean(
    const float* __restrict__ z, float* __restrict__ out)
{
    int tid = threadIdx.x;
    int c = tid % 40;
    int r0 = tid / 40;   // 0..7
    float s = 0.f;
    for (int row = blockIdx.x * 8 + r0; row < N_NODES; row += gridDim.x * 8)
        s += z[row * 40 + c];
    __shared__ float sh[320];
    sh[tid] = s;
    __syncthreads();
    if (r0 == 0) {
        float t = 0.f;
#pragma unroll
        for (int i = 0; i < 8; i++) t += sh[i * 40 + c];
        atomicAdd(&out[c], t * (1.0f / (float)N_NODES));
    }
}

// ---------------- launch ----------------------------------------------------
extern "C" void kernel_launch(void* const* d_in, const int* in_sizes, int n_in,
                              void* d_out, int out_size)
{
    const float* x  = (const float*)d_in[0];
    const void*  ei = d_in[1];
    const float* W0 = (const float*)d_in[2];
    const float* b0 = (const float*)d_in[3];
    const float* W1 = (const float*)d_in[4];
    const float* b1 = (const float*)d_in[5];
    const float* W2 = (const float*)d_in[6];
    const float* b2 = (const float*)d_in[7];
    float* out = (float*)d_out;

    float* bufA; cudaGetSymbolAddress((void**)&bufA, g_bufA);
    float* bufB; cudaGetSymbolAddress((void**)&bufB, g_bufB);

    const int edgeBlocks  = (N_EDGES + 255) / 256;   // 3125
    const int gemmBlocks  = (N_NODES + 127) / 128;   // 391
    const int gemm40Blk   = (N_NODES + 63) / 64;     // 782
    const int aggBlocks   = (N_NODES + 7) / 8;       // 6250

    // --- CSR build + normalization (stage decoded edges in bufA) ---
    int2* stage = (int2*)bufA;
    k_zero_detect<<<NB_SCAN, 256>>>((const unsigned*)ei);
    k_decode_count<<<edgeBlocks, 256>>>(ei, stage);
    k_scan_local<<<NB_SCAN, 256>>>();
    k_scan_bsum<<<1, 256>>>();
    k_scan_add<<<NB_SCAN, 256>>>();
    k_fill<<<edgeBlocks, 256>>>(stage);

    // --- layer 1: x -> bufB (h1) ---
    k_gemm128<<<gemmBlocks, 256>>>(x, W0, bufA);
    k_agg128<<<aggBlocks, 256>>>(bufA, b0, bufB, 1);

    // --- layer 2: bufB -> bufB (h2) ---
    k_gemm128<<<gemmBlocks, 256>>>(bufB, W1, bufA);
    k_agg128<<<aggBlocks, 256>>>(bufA, b1, bufB, 1);

    // --- layer 3: bufB -> bufB (z, 40 ch) ---
    k_gemm40<<<gemm40Blk, 320>>>(bufB, W2, bufA);
    k_agg40<<<aggBlocks, 256>>>(bufA, bufB);

    // --- mean pool (+b2) ---
    k_zero_out<<<1, 64>>>(out, b2);
    k_mean<<<256, 320>>>(bufB, out);
}

// round 6
// speedup vs baseline: 1.9136x; 1.1780x over previous
#include <cuda_runtime.h>
#include <cuda_bf16.h>
#include <cstdint>

#define N_NODES 50000
#define N_EDGES 800000
#define HID 128
#define COUT 40
#define NB_SCAN 196   // ceil(50000/256)

typedef unsigned long long ull;

// ---------------- device scratch (static, allocation-free) ----------------
__device__ float g_dis[N_NODES];
__device__ float g_cwa[N_NODES];         // sum over out-edges of dis[col]
__device__ int   g_cnt[N_NODES];
__device__ int   g_off[N_NODES + 1];
__device__ int   g_cur[N_NODES];
__device__ int   g_bsum[NB_SCAN];
__device__ __align__(16) int2 g_epair[N_EDGES];  // {src, norm bits} CSR-ordered
__device__ float g_v[HID];               // weighted h2 reduction
__device__ int   g_flag;                 // 1 = edge_index is int64, 0 = int32
__device__ float g_bufA[N_NODES * HID];  // xw scratch (int2 staging in setup)
__device__ float g_bufB[N_NODES * HID];  // h scratch

// ---------------- small helpers ----------------
__device__ __forceinline__ ull pack2(float lo, float hi) {
    ull r; asm("mov.b64 %0,{%1,%2};" : "=l"(r) : "f"(lo), "f"(hi)); return r;
}
__device__ __forceinline__ void unpack2(ull v, float& lo, float& hi) {
    asm("mov.b64 {%0,%1},%2;" : "=f"(lo), "=f"(hi) : "l"(v));
}
__device__ __forceinline__ ull fma2(ull a, ull b, ull c) {
    ull d; asm("fma.rn.f32x2 %0,%1,%2,%3;" : "=l"(d) : "l"(a), "l"(b), "l"(c)); return d;
}

__device__ __forceinline__ void decode_edge(const void* ei, int e, int& r, int& c) {
    if (g_flag) {
        const long long* p = (const long long*)ei;
        r = (int)p[e];
        c = (int)p[N_EDGES + e];
    } else {
        const int* p = (const int*)ei;
        r = p[e];
        c = p[N_EDGES + e];
    }
}

// ---------------- setup kernels ----------------
// Zero counters/accumulators; block 0 also detects edge_index element width
// (int64 => every odd 32-bit word is zero, values < 50000).
__global__ void k_zero_detect(const unsigned* __restrict__ ei) {
    int i = blockIdx.x * 256 + threadIdx.x;
    if (i < N_NODES) { g_cnt[i] = 0; g_cwa[i] = 0.f; }
    if (blockIdx.x == 0 && threadIdx.x < 32) {
        int lane = threadIdx.x;
        unsigned nz = (ei[2 * lane + 1] != 0u) | (ei[2 * (lane + 32) + 1] != 0u);
        unsigned any = __ballot_sync(0xffffffffu, nz);
        if (lane == 0) g_flag = (any == 0u) ? 1 : 0;
    }
}

// Decode once into staging (int2 per edge) + histogram destinations.
__global__ void k_decode_count(const void* __restrict__ ei, int2* __restrict__ stage) {
    int e = blockIdx.x * blockDim.x + threadIdx.x;
    if (e >= N_EDGES) return;
    int r, c;
    decode_edge(ei, e, r, c);
    stage[e] = make_int2(r, c);
    atomicAdd(&g_cnt[c], 1);
}

__global__ void k_scan_local() {
    __shared__ int s[256];
    int i = blockIdx.x * 256 + threadIdx.x;
    int v = (i < N_NODES) ? g_cnt[i] : 0;
    s[threadIdx.x] = v;
    __syncthreads();
    for (int d = 1; d < 256; d <<= 1) {
        int t = (threadIdx.x >= d) ? s[threadIdx.x - d] : 0;
        __syncthreads();
        s[threadIdx.x] += t;
        __syncthreads();
    }
    if (i < N_NODES) g_off[i] = s[threadIdx.x] - v;  // exclusive within block
    if (threadIdx.x == 255) g_bsum[blockIdx.x] = s[255];
}

// Each block redundantly scans the 196 block sums (cheap), then applies its
// exclusive prefix; also derives dis[] and zeroes g_v.
__global__ void k_scan_add() {
    __shared__ int s[256];
    int tid = threadIdx.x;
    int v = (tid < NB_SCAN) ? g_bsum[tid] : 0;
    s[tid] = v;
    __syncthreads();
    for (int d = 1; d < 256; d <<= 1) {
        int t = (tid >= d) ? s[tid - d] : 0;
        __syncthreads();
        s[tid] += t;
        __syncthreads();
    }
    int base = (blockIdx.x == 0) ? 0 : s[blockIdx.x - 1];
    int i = blockIdx.x * 256 + tid;
    if (i < N_NODES) {
        int o = g_off[i] + base;
        g_off[i] = o;
        g_cur[i] = o;
        g_dis[i] = rsqrtf((float)g_cnt[i] + 1.0f);
    }
    if (i == 0) g_off[N_NODES] = N_EDGES;
    if (i < HID) g_v[i] = 0.f;
}

// Fill CSR + accumulate column-sum weights for the layer-3 collapse.
__global__ void k_fill(const int2* __restrict__ stage) {
    int e = blockIdx.x * blockDim.x + threadIdx.x;
    if (e >= N_EDGES) return;
    int2 rc = stage[e];
    float dr = g_dis[rc.x], dc = g_dis[rc.y];
    int pos = atomicAdd(&g_cur[rc.y], 1);
    g_epair[pos] = make_int2(rc.x, __float_as_int(dr * dc));
    atomicAdd(&g_cwa[rc.x], dc);
}

// ---------------- GEMM: [N,128] @ [128,128] -> xw -------------------------
// 128x128 tile, 256 threads, 8x8 microtile, packed f32x2 FMA, 2 blocks/SM.
__global__ __launch_bounds__(256, 2) void k_gemm128(
    const float* __restrict__ A, const float* __restrict__ W,
    float* __restrict__ xw)
{
    __shared__ float sW[32 * 128];
    __shared__ float sA[32 * 128];   // k-major, row XOR-swizzled

    int tid = threadIdx.x;
    int ty = tid >> 4;           // 0..15 row group
    int tx = tid & 15;           // 0..15 col group
    int rb = blockIdx.x * 128;

    ull acc[8][4];
#pragma unroll
    for (int i = 0; i < 8; i++)
#pragma unroll
        for (int j = 0; j < 4; j++) acc[i][j] = 0ull;

    const float4* A4 = (const float4*)A;

    for (int kk = 0; kk < 4; kk++) {
        __syncthreads();
        {
            const float4* Wg = (const float4*)(W + kk * 32 * 128);
            float4* sW4 = (float4*)sW;
#pragma unroll
            for (int t = 0; t < 4; t++) sW4[tid + t * 256] = Wg[tid + t * 256];
        }
#pragma unroll
        for (int t = 0; t < 4; t++) {
            int idx = tid + t * 256;         // 0..1023
            int row = idx >> 3, q = idx & 7;
            int gr = rb + row;
            float4 v = make_float4(0.f, 0.f, 0.f, 0.f);
            if (gr < N_NODES) v = A4[gr * 32 + kk * 8 + q];
            int xr = row ^ (q << 2);
            sA[(q * 4 + 0) * 128 + xr] = v.x;
            sA[(q * 4 + 1) * 128 + xr] = v.y;
            sA[(q * 4 + 2) * 128 + xr] = v.z;
            sA[(q * 4 + 3) * 128 + xr] = v.w;
        }
        __syncthreads();
#pragma unroll 4
        for (int kl = 0; kl < 32; kl++) {
            int q = kl >> 2;
            float4 a0 = *(const float4*)&sA[kl * 128 + ((ty * 8) ^ (q << 2))];
            float4 a1 = *(const float4*)&sA[kl * 128 + ((ty * 8 + 4) ^ (q << 2))];
            ulonglong2 w01 = *(const ulonglong2*)&sW[kl * 128 + tx * 8];
            ulonglong2 w23 = *(const ulonglong2*)&sW[kl * 128 + tx * 8 + 4];
            ull wp0 = w01.x, wp1 = w01.y, wp2 = w23.x, wp3 = w23.y;
            float ar[8] = {a0.x, a0.y, a0.z, a0.w, a1.x, a1.y, a1.z, a1.w};
#pragma unroll
            for (int i = 0; i < 8; i++) {
                ull ap = pack2(ar[i], ar[i]);
                acc[i][0] = fma2(ap, wp0, acc[i][0]);
                acc[i][1] = fma2(ap, wp1, acc[i][1]);
                acc[i][2] = fma2(ap, wp2, acc[i][2]);
                acc[i][3] = fma2(ap, wp3, acc[i][3]);
            }
        }
    }

    float4* xw4 = (float4*)xw;
#pragma unroll
    for (int i = 0; i < 8; i++) {
        int gr = rb + ty * 8 + i;
        if (gr >= N_NODES) continue;
        float4 o0, o1;
        unpack2(acc[i][0], o0.x, o0.y);
        unpack2(acc[i][1], o0.z, o0.w);
        unpack2(acc[i][2], o1.x, o1.y);
        unpack2(acc[i][3], o1.z, o1.w);
        xw4[gr * 32 + tx * 2] = o0;
        xw4[gr * 32 + tx * 2 + 1] = o1;
    }
}

// ---------------- CSR aggregate (warp per destination node) ---------------
__global__ __launch_bounds__(256) void k_agg128(
    const float* __restrict__ xw, const float* __restrict__ bias,
    float* __restrict__ h)
{
    int w = blockIdx.x * 8 + (threadIdx.x >> 5);
    int lane = threadIdx.x & 31;
    if (w >= N_NODES) return;
    const float4* xw4 = (const float4*)xw;
    float d = g_dis[w];
    float d2 = d * d;
    float4 self = xw4[w * 32 + lane];
    float4 acc = make_float4(self.x * d2, self.y * d2, self.z * d2, self.w * d2);
    int beg = g_off[w], end = g_off[w + 1];
    int e = beg;
    if ((e & 1) && e < end) {
        int2 p = g_epair[e];
        float nw = __int_as_float(p.y);
        float4 v = xw4[p.x * 32 + lane];
        acc.x += v.x * nw; acc.y += v.y * nw; acc.z += v.z * nw; acc.w += v.w * nw;
        e++;
    }
    for (; e + 4 <= end; e += 4) {
        int4 pa = *(const int4*)&g_epair[e];       // edges e, e+1
        int4 pb = *(const int4*)&g_epair[e + 2];   // edges e+2, e+3
        float4 v0 = xw4[pa.x * 32 + lane];
        float4 v1 = xw4[pa.z * 32 + lane];
        float4 v2 = xw4[pb.x * 32 + lane];
        float4 v3 = xw4[pb.z * 32 + lane];
        float n0 = __int_as_float(pa.y), n1 = __int_as_float(pa.w);
        float n2 = __int_as_float(pb.y), n3 = __int_as_float(pb.w);
        acc.x += v0.x * n0; acc.y += v0.y * n0; acc.z += v0.z * n0; acc.w += v0.w * n0;
        acc.x += v1.x * n1; acc.y += v1.y * n1; acc.z += v1.z * n1; acc.w += v1.w * n1;
        acc.x += v2.x * n2; acc.y += v2.y * n2; acc.z += v2.z * n2; acc.w += v2.w * n2;
        acc.x += v3.x * n3; acc.y += v3.y * n3; acc.z += v3.z * n3; acc.w += v3.w * n3;
    }
    for (; e < end; e++) {
        int2 p = g_epair[e];
        float nw = __int_as_float(p.y);
        float4 v = xw4[p.x * 32 + lane];
        acc.x += v.x * nw; acc.y += v.y * nw; acc.z += v.z * nw; acc.w += v.w * nw;
    }
    float4 bb = ((const float4*)bias)[lane];
    acc.x = fmaxf(acc.x + bb.x, 0.f);
    acc.y = fmaxf(acc.y + bb.y, 0.f);
    acc.z = fmaxf(acc.z + bb.z, 0.f);
    acc.w = fmaxf(acc.w + bb.w, 0.f);
    ((float4*)h)[w * 32 + lane] = acc;
}

// ---------------- layer-3 collapse: v[k] = sum_m cw[m] * h2[m,k] -----------
__global__ __launch_bounds__(256) void k_wred(const float* __restrict__ h2) {
    __shared__ float sv[256];
    int k = threadIdx.x & 127;
    int half = threadIdx.x >> 7;
    float acc = 0.f;
    int m0 = blockIdx.x * 128;
    int mend = min(m0 + 128, N_NODES);
    for (int m = m0 + half; m < mend; m += 2) {
        float d = g_dis[m];
        float wn = d * (g_cwa[m] + d);
        acc += wn * h2[m * HID + k];
    }
    sv[threadIdx.x] = acc;
    __syncthreads();
    if (half == 0) atomicAdd(&g_v[k], acc + sv[128 + k]);
}

// out[c] = b2[c] + (1/N) * sum_k v[k] * W2[k,c]
__global__ void k_finish(const float* __restrict__ W2,
                         const float* __restrict__ b2, float* __restrict__ out) {
    int c = threadIdx.x;
    if (c >= COUT) return;
    float acc = 0.f;
#pragma unroll 4
    for (int k = 0; k < HID; k++) acc += g_v[k] * W2[k * COUT + c];
    out[c] = b2[c] + acc * (1.0f / (float)N_NODES);
}

// ---------------- launch ----------------------------------------------------
extern "C" void kernel_launch(void* const* d_in, const int* in_sizes, int n_in,
                              void* d_out, int out_size)
{
    const float* x  = (const float*)d_in[0];
    const void*  ei = d_in[1];
    const float* W0 = (const float*)d_in[2];
    const float* b0 = (const float*)d_in[3];
    const float* W1 = (const float*)d_in[4];
    const float* b1 = (const float*)d_in[5];
    const float* W2 = (const float*)d_in[6];
    const float* b2 = (const float*)d_in[7];
    float* out = (float*)d_out;

    float* bufA; cudaGetSymbolAddress((void**)&bufA, g_bufA);
    float* bufB; cudaGetSymbolAddress((void**)&bufB, g_bufB);

    const int edgeBlocks = (N_EDGES + 255) / 256;   // 3125
    const int gemmBlocks = (N_NODES + 127) / 128;   // 391
    const int aggBlocks  = (N_NODES + 7) / 8;       // 6250
    const int wredBlocks = (N_NODES + 127) / 128;   // 391

    // --- CSR build + normalization (stage decoded edges in bufA) ---
    int2* stage = (int2*)bufA;
    k_zero_detect<<<NB_SCAN, 256>>>((const unsigned*)ei);
    k_decode_count<<<edgeBlocks, 256>>>(ei, stage);
    k_scan_local<<<NB_SCAN, 256>>>();
    k_scan_add<<<NB_SCAN, 256>>>();
    k_fill<<<edgeBlocks, 256>>>(stage);

    // --- layer 1: x -> bufB (h1) ---
    k_gemm128<<<gemmBlocks, 256>>>(x, W0, bufA);
    k_agg128<<<aggBlocks, 256>>>(bufA, b0, bufB);

    // --- layer 2: bufB -> bufB (h2) ---
    k_gemm128<<<gemmBlocks, 256>>>(bufB, W1, bufA);
    k_agg128<<<aggBlocks, 256>>>(bufA, b1, bufB);

    // --- layer 3 (collapsed): weighted reduce + tiny matvec ---
    k_wred<<<wredBlocks, 256>>>(bufB);
    k_finish<<<1, 64>>>(W2, b2, out);
}

// round 7
// speedup vs baseline: 2.2560x; 1.1790x over previous
#include <cuda_runtime.h>
#include <cuda_bf16.h>
#include <cuda_fp16.h>
#include <cstdint>

#define N_NODES 50000
#define N_EDGES 800000
#define HID 128
#define COUT 40
#define NB_SCAN 196   // ceil(50000/256)

typedef unsigned long long ull;

// ---------------- device scratch (static, allocation-free) ----------------
__device__ float g_dis[N_NODES];
__device__ float g_cwa[N_NODES];         // sum over out-edges of dis[col]
__device__ int   g_cnt[N_NODES];
__device__ int   g_off[N_NODES + 1];
__device__ int   g_cur[N_NODES];
__device__ int   g_bsum[NB_SCAN];
__device__ __align__(16) unsigned g_emeta[N_EDGES]; // {fp16 norm | 16-bit src}
__device__ float g_v[HID];               // weighted h2 reduction
__device__ int   g_flag;                 // 1 = edge_index is int64, 0 = int32
__device__ float g_bufA[N_NODES * HID];  // xw (bf16) / int2 staging
__device__ float g_bufB[N_NODES * HID];  // h scratch (fp32)

// ---------------- small helpers ----------------
__device__ __forceinline__ ull pack2(float lo, float hi) {
    ull r; asm("mov.b64 %0,{%1,%2};" : "=l"(r) : "f"(lo), "f"(hi)); return r;
}
__device__ __forceinline__ void unpack2(ull v, float& lo, float& hi) {
    asm("mov.b64 {%0,%1},%2;" : "=f"(lo), "=f"(hi) : "l"(v));
}
__device__ __forceinline__ ull fma2(ull a, ull b, ull c) {
    ull d; asm("fma.rn.f32x2 %0,%1,%2,%3;" : "=l"(d) : "l"(a), "l"(b), "l"(c)); return d;
}

__device__ __forceinline__ void decode_edge(const void* ei, int e, int& r, int& c) {
    if (g_flag) {
        const long long* p = (const long long*)ei;
        r = (int)p[e];
        c = (int)p[N_EDGES + e];
    } else {
        const int* p = (const int*)ei;
        r = p[e];
        c = p[N_EDGES + e];
    }
}

// ---------------- setup kernels ----------------
__global__ void k_zero_detect(const unsigned* __restrict__ ei) {
    int i = blockIdx.x * 256 + threadIdx.x;
    if (i < N_NODES) { g_cnt[i] = 0; g_cwa[i] = 0.f; }
    if (blockIdx.x == 0 && threadIdx.x < 32) {
        int lane = threadIdx.x;
        unsigned nz = (ei[2 * lane + 1] != 0u) | (ei[2 * (lane + 32) + 1] != 0u);
        unsigned any = __ballot_sync(0xffffffffu, nz);
        if (lane == 0) g_flag = (any == 0u) ? 1 : 0;
    }
}

__global__ void k_decode_count(const void* __restrict__ ei, int2* __restrict__ stage) {
    int e = blockIdx.x * blockDim.x + threadIdx.x;
    if (e >= N_EDGES) return;
    int r, c;
    decode_edge(ei, e, r, c);
    stage[e] = make_int2(r, c);
    atomicAdd(&g_cnt[c], 1);
}

__global__ void k_scan_local() {
    __shared__ int s[256];
    int i = blockIdx.x * 256 + threadIdx.x;
    int v = (i < N_NODES) ? g_cnt[i] : 0;
    s[threadIdx.x] = v;
    __syncthreads();
    for (int d = 1; d < 256; d <<= 1) {
        int t = (threadIdx.x >= d) ? s[threadIdx.x - d] : 0;
        __syncthreads();
        s[threadIdx.x] += t;
        __syncthreads();
    }
    if (i < N_NODES) g_off[i] = s[threadIdx.x] - v;
    if (threadIdx.x == 255) g_bsum[blockIdx.x] = s[255];
}

// Each block redundantly scans the 196 block sums, applies its prefix,
// derives dis[], zeroes g_v.
__global__ void k_scan_add() {
    __shared__ int s[256];
    int tid = threadIdx.x;
    int v = (tid < NB_SCAN) ? g_bsum[tid] : 0;
    s[tid] = v;
    __syncthreads();
    for (int d = 1; d < 256; d <<= 1) {
        int t = (tid >= d) ? s[tid - d] : 0;
        __syncthreads();
        s[tid] += t;
        __syncthreads();
    }
    int base = (blockIdx.x == 0) ? 0 : s[blockIdx.x - 1];
    int i = blockIdx.x * 256 + tid;
    if (i < N_NODES) {
        int o = g_off[i] + base;
        g_off[i] = o;
        g_cur[i] = o;
        g_dis[i] = rsqrtf((float)g_cnt[i] + 1.0f);
    }
    if (i == 0) g_off[N_NODES] = N_EDGES;
    if (i < HID) g_v[i] = 0.f;
}

// Fill CSR (packed meta) + accumulate column-sum weights for layer-3 collapse.
__global__ void k_fill(const int2* __restrict__ stage) {
    int e = blockIdx.x * blockDim.x + threadIdx.x;
    if (e >= N_EDGES) return;
    int2 rc = stage[e];
    float dr = g_dis[rc.x], dc = g_dis[rc.y];
    int pos = atomicAdd(&g_cur[rc.y], 1);
    unsigned short hn = __half_as_ushort(__float2half_rn(dr * dc));
    g_emeta[pos] = (unsigned)rc.x | ((unsigned)hn << 16);
    atomicAdd(&g_cwa[rc.x], dc);
}

// ---------------- GEMM: [N,128] fp32 @ [128,128] -> xw bf16 ----------------
// 128x128 tile, 256 threads, 8x8 microtile, packed f32x2 FMA, 2 blocks/SM.
__global__ __launch_bounds__(256, 2) void k_gemm128(
    const float* __restrict__ A, const float* __restrict__ W,
    __nv_bfloat16* __restrict__ xwh)
{
    __shared__ float sW[32 * 128];
    __shared__ float sA[32 * 128];   // k-major, row XOR-swizzled

    int tid = threadIdx.x;
    int ty = tid >> 4;           // 0..15 row group
    int tx = tid & 15;           // 0..15 col group
    int rb = blockIdx.x * 128;

    ull acc[8][4];
#pragma unroll
    for (int i = 0; i < 8; i++)
#pragma unroll
        for (int j = 0; j < 4; j++) acc[i][j] = 0ull;

    const float4* A4 = (const float4*)A;

    for (int kk = 0; kk < 4; kk++) {
        __syncthreads();
        {
            const float4* Wg = (const float4*)(W + kk * 32 * 128);
            float4* sW4 = (float4*)sW;
#pragma unroll
            for (int t = 0; t < 4; t++) sW4[tid + t * 256] = Wg[tid + t * 256];
        }
#pragma unroll
        for (int t = 0; t < 4; t++) {
            int idx = tid + t * 256;         // 0..1023
            int row = idx >> 3, q = idx & 7;
            int gr = rb + row;
            float4 v = make_float4(0.f, 0.f, 0.f, 0.f);
            if (gr < N_NODES) v = A4[gr * 32 + kk * 8 + q];
            int xr = row ^ (q << 2);
            sA[(q * 4 + 0) * 128 + xr] = v.x;
            sA[(q * 4 + 1) * 128 + xr] = v.y;
            sA[(q * 4 + 2) * 128 + xr] = v.z;
            sA[(q * 4 + 3) * 128 + xr] = v.w;
        }
        __syncthreads();
#pragma unroll 4
        for (int kl = 0; kl < 32; kl++) {
            int q = kl >> 2;
            float4 a0 = *(const float4*)&sA[kl * 128 + ((ty * 8) ^ (q << 2))];
            float4 a1 = *(const float4*)&sA[kl * 128 + ((ty * 8 + 4) ^ (q << 2))];
            ulonglong2 w01 = *(const ulonglong2*)&sW[kl * 128 + tx * 8];
            ulonglong2 w23 = *(const ulonglong2*)&sW[kl * 128 + tx * 8 + 4];
            ull wp0 = w01.x, wp1 = w01.y, wp2 = w23.x, wp3 = w23.y;
            float ar[8] = {a0.x, a0.y, a0.z, a0.w, a1.x, a1.y, a1.z, a1.w};
#pragma unroll
            for (int i = 0; i < 8; i++) {
                ull ap = pack2(ar[i], ar[i]);
                acc[i][0] = fma2(ap, wp0, acc[i][0]);
                acc[i][1] = fma2(ap, wp1, acc[i][1]);
                acc[i][2] = fma2(ap, wp2, acc[i][2]);
                acc[i][3] = fma2(ap, wp3, acc[i][3]);
            }
        }
    }

    // epilogue: convert to bf16, one uint4 (8 bf16) store per row
    uint4* out4 = (uint4*)xwh;
#pragma unroll
    for (int i = 0; i < 8; i++) {
        int gr = rb + ty * 8 + i;
        if (gr >= N_NODES) continue;
        uint4 st;
        float lo, hi;
        unpack2(acc[i][0], lo, hi);
        { __nv_bfloat162 b = __float22bfloat162_rn(make_float2(lo, hi)); st.x = *(unsigned*)&b; }
        unpack2(acc[i][1], lo, hi);
        { __nv_bfloat162 b = __float22bfloat162_rn(make_float2(lo, hi)); st.y = *(unsigned*)&b; }
        unpack2(acc[i][2], lo, hi);
        { __nv_bfloat162 b = __float22bfloat162_rn(make_float2(lo, hi)); st.z = *(unsigned*)&b; }
        unpack2(acc[i][3], lo, hi);
        { __nv_bfloat162 b = __float22bfloat162_rn(make_float2(lo, hi)); st.w = *(unsigned*)&b; }
        out4[gr * 16 + tx] = st;
    }
}

// ---------------- CSR aggregate (warp per node, bf16 gather) ---------------
__device__ __forceinline__ void acc_bf16(float4& acc, uint2 v, float nw) {
    float f0 = __uint_as_float(v.x << 16);
    float f1 = __uint_as_float(v.x & 0xFFFF0000u);
    float f2 = __uint_as_float(v.y << 16);
    float f3 = __uint_as_float(v.y & 0xFFFF0000u);
    acc.x += f0 * nw; acc.y += f1 * nw; acc.z += f2 * nw; acc.w += f3 * nw;
}
__device__ __forceinline__ float meta_norm(unsigned m) {
    return __half2float(__ushort_as_half((unsigned short)(m >> 16)));
}

__global__ __launch_bounds__(256) void k_agg128(
    const __nv_bfloat16* __restrict__ xwh, const float* __restrict__ bias,
    float* __restrict__ h)
{
    int w = blockIdx.x * 8 + (threadIdx.x >> 5);
    int lane = threadIdx.x & 31;
    if (w >= N_NODES) return;
    const uint2* xw2 = (const uint2*)xwh;   // row = 16 uint2 (128 bf16)
    float d = g_dis[w];
    float d2 = d * d;
    float4 acc = make_float4(0.f, 0.f, 0.f, 0.f);
    acc_bf16(acc, xw2[w * 16 + (lane & 15)], d2);   // self term (lanes 16-31 dup, masked below)
    // NOTE: row has only 16 uint2; lanes 0..15 handle ch 0..63? -- no:
    // 128 bf16 / 32 lanes = 4 ch per lane = 1 uint2 per lane; row = 32 uint2? 
    // 128 bf16 = 256B = 32 uint2. Correct stride is 32.
    // (computed below with stride 32; the line above is replaced)
    acc = make_float4(0.f, 0.f, 0.f, 0.f);
    acc_bf16(acc, ((const uint2*)xwh)[w * 32 + lane], d2);
    int beg = g_off[w], end = g_off[w + 1];
    int e = beg;
    while ((e & 3) && e < end) {
        unsigned m = g_emeta[e];
        acc_bf16(acc, ((const uint2*)xwh)[(int)(m & 0xFFFFu) * 32 + lane], meta_norm(m));
        e++;
    }
    for (; e + 4 <= end; e += 4) {
        uint4 mm = *(const uint4*)&g_emeta[e];
        uint2 v0 = ((const uint2*)xwh)[(int)(mm.x & 0xFFFFu) * 32 + lane];
        uint2 v1 = ((const uint2*)xwh)[(int)(mm.y & 0xFFFFu) * 32 + lane];
        uint2 v2 = ((const uint2*)xwh)[(int)(mm.z & 0xFFFFu) * 32 + lane];
        uint2 v3 = ((const uint2*)xwh)[(int)(mm.w & 0xFFFFu) * 32 + lane];
        acc_bf16(acc, v0, meta_norm(mm.x));
        acc_bf16(acc, v1, meta_norm(mm.y));
        acc_bf16(acc, v2, meta_norm(mm.z));
        acc_bf16(acc, v3, meta_norm(mm.w));
    }
    for (; e < end; e++) {
        unsigned m = g_emeta[e];
        acc_bf16(acc, ((const uint2*)xwh)[(int)(m & 0xFFFFu) * 32 + lane], meta_norm(m));
    }
    float4 bb = ((const float4*)bias)[lane];
    acc.x = fmaxf(acc.x + bb.x, 0.f);
    acc.y = fmaxf(acc.y + bb.y, 0.f);
    acc.z = fmaxf(acc.z + bb.z, 0.f);
    acc.w = fmaxf(acc.w + bb.w, 0.f);
    ((float4*)h)[w * 32 + lane] = acc;
}

// ---------------- layer-3 collapse: v[k] = sum_m cw[m] * h2[m,k] -----------
__global__ __launch_bounds__(256) void k_wred(const float* __restrict__ h2) {
    __shared__ float sv[256];
    int k = threadIdx.x & 127;
    int half = threadIdx.x >> 7;
    float acc = 0.f;
    int m0 = blockIdx.x * 128;
    int mend = min(m0 + 128, N_NODES);
    for (int m = m0 + half; m < mend; m += 2) {
        float d = g_dis[m];
        float wn = d * (g_cwa[m] + d);
        acc += wn * h2[m * HID + k];
    }
    sv[threadIdx.x] = acc;
    __syncthreads();
    if (half == 0) atomicAdd(&g_v[k], acc + sv[128 + k]);
}

// out[c] = b2[c] + (1/N) * sum_k v[k] * W2[k,c]
__global__ void k_finish(const float* __restrict__ W2,
                         const float* __restrict__ b2, float* __restrict__ out) {
    int c = threadIdx.x;
    if (c >= COUT) return;
    float acc = 0.f;
#pragma unroll 4
    for (int k = 0; k < HID; k++) acc += g_v[k] * W2[k * COUT + c];
    out[c] = b2[c] + acc * (1.0f / (float)N_NODES);
}

// ---------------- launch ----------------------------------------------------
extern "C" void kernel_launch(void* const* d_in, const int* in_sizes, int n_in,
                              void* d_out, int out_size)
{
    const float* x  = (const float*)d_in[0];
    const void*  ei = d_in[1];
    const float* W0 = (const float*)d_in[2];
    const float* b0 = (const float*)d_in[3];
    const float* W1 = (const float*)d_in[4];
    const float* b1 = (const float*)d_in[5];
    const float* W2 = (const float*)d_in[6];
    const float* b2 = (const float*)d_in[7];
    float* out = (float*)d_out;

    float* bufA; cudaGetSymbolAddress((void**)&bufA, g_bufA);
    float* bufB; cudaGetSymbolAddress((void**)&bufB, g_bufB);

    const int edgeBlocks = (N_EDGES + 255) / 256;   // 3125
    const int gemmBlocks = (N_NODES + 127) / 128;   // 391
    const int aggBlocks  = (N_NODES + 7) / 8;       // 6250
    const int wredBlocks = (N_NODES + 127) / 128;   // 391

    // --- CSR build + normalization (stage decoded edges in bufA) ---
    int2* stage = (int2*)bufA;
    k_zero_detect<<<NB_SCAN, 256>>>((const unsigned*)ei);
    k_decode_count<<<edgeBlocks, 256>>>(ei, stage);
    k_scan_local<<<NB_SCAN, 256>>>();
    k_scan_add<<<NB_SCAN, 256>>>();
    k_fill<<<edgeBlocks, 256>>>(stage);

    __nv_bfloat16* xwh = (__nv_bfloat16*)bufA;

    // --- layer 1: x -> bufB (h1) ---
    k_gemm128<<<gemmBlocks, 256>>>(x, W0, xwh);
    k_agg128<<<aggBlocks, 256>>>(xwh, b0, bufB);

    // --- layer 2: bufB -> bufB (h2) ---
    k_gemm128<<<gemmBlocks, 256>>>(bufB, W1, xwh);
    k_agg128<<<aggBlocks, 256>>>(xwh, b1, bufB);

    // --- layer 3 (collapsed): weighted reduce + tiny matvec ---
    k_wred<<<wredBlocks, 256>>>(bufB);
    k_finish<<<1, 64>>>(W2, b2, out);
}